// round 1
// baseline (speedup 1.0000x reference)
#include <cuda_runtime.h>
#include <cstdint>

// Problem constants
#define B_  32
#define S_  2048
#define C_  1024
#define G_  16
#define GS_ 64          // channels per group
#define K_  256         // top-k kept per (batch, group)

// Scratch (no cudaMalloc allowed)
__device__ float         g_norms[B_ * G_ * S_];   // (B*g, S) row-major, 4 MB
__device__ unsigned char g_mask [B_ * G_ * S_];   // 1 MB

// ---------------------------------------------------------------------------
// K1: sum-of-squares per (b, s, group). One block per (b,s); 256 threads,
// each loads one float4 (4 contiguous channels). 16 threads cover a group.
// ---------------------------------------------------------------------------
__global__ __launch_bounds__(256) void k_norms(const float* __restrict__ x) {
    const int bs = blockIdx.x;              // b*S + s
    const int t  = threadIdx.x;             // 0..255
    const float4 v = reinterpret_cast<const float4*>(x + (size_t)bs * C_)[t];
    float ss = v.x * v.x + v.y * v.y + v.z * v.z + v.w * v.w;
    // reduce across the 16 threads of this group (lanes t..t|15 within warp)
    #pragma unroll
    for (int off = 8; off > 0; off >>= 1)
        ss += __shfl_down_sync(0xffffffffu, ss, off, 16);
    if ((t & 15) == 0) {
        const int g = t >> 4;               // 0..15
        const int b = bs / S_;
        const int s = bs - b * S_;
        g_norms[((b << 4) + g) * S_ + s] = ss;
    }
}

// ---------------------------------------------------------------------------
// K2: per row of 2048 norms, bitonic sort a copy in smem (ascending),
// threshold = element [S-K]. Then build the byte mask with exact-K ties.
// 512 blocks x 1024 threads.
// ---------------------------------------------------------------------------
__global__ __launch_bounds__(1024) void k_select() {
    __shared__ float srt[S_];
    __shared__ float orig[S_];
    __shared__ int   n_gt;
    __shared__ int   eq_cnt;

    const int row = blockIdx.x;             // 0..511
    const int tid = threadIdx.x;            // 0..1023
    const float* nr = g_norms + (size_t)row * S_;

    #pragma unroll
    for (int i = tid; i < S_; i += 1024) {
        float v = nr[i];
        srt[i]  = v;
        orig[i] = v;
    }
    if (tid == 0) { n_gt = 0; eq_cnt = 0; }
    __syncthreads();

    // bitonic sort ascending, n = 2048
    for (int k = 2; k <= S_; k <<= 1) {
        for (int j = k >> 1; j > 0; j >>= 1) {
            #pragma unroll
            for (int idx = tid; idx < S_; idx += 1024) {
                int ixj = idx ^ j;
                if (ixj > idx) {
                    bool up = ((idx & k) == 0);
                    float a = srt[idx], b = srt[ixj];
                    if ((a > b) == up) { srt[idx] = b; srt[ixj] = a; }
                }
            }
            __syncthreads();
        }
    }

    const float thr = srt[S_ - K_];

    // count strictly-greater (for exact-K tie fill)
    int loc = 0;
    #pragma unroll
    for (int i = tid; i < S_; i += 1024)
        loc += (orig[i] > thr) ? 1 : 0;
    #pragma unroll
    for (int off = 16; off > 0; off >>= 1)
        loc += __shfl_down_sync(0xffffffffu, loc, off);
    if ((tid & 31) == 0) atomicAdd(&n_gt, loc);
    __syncthreads();

    const int ngt = n_gt;
    unsigned char* mrow = g_mask + (size_t)row * S_;
    #pragma unroll
    for (int i = tid; i < S_; i += 1024) {
        float v = orig[i];
        unsigned char m = 0;
        if (v > thr) m = 1;
        else if (v == thr) {
            int p = atomicAdd(&eq_cnt, 1);
            m = (ngt + p < K_) ? 1 : 0;
        }
        mrow[i] = m;
    }
}

// ---------------------------------------------------------------------------
// K3: apply mask. One block per (b,s); thread t handles channels [4t,4t+4)
// (group g = t/16). Read x only when mask set; always write.
// ---------------------------------------------------------------------------
__global__ __launch_bounds__(256) void k_apply(const float* __restrict__ x,
                                               float* __restrict__ out) {
    const int bs = blockIdx.x;
    const int t  = threadIdx.x;
    const int g  = t >> 4;
    const int b  = bs / S_;
    const int s  = bs - b * S_;
    const unsigned char m = g_mask[((b << 4) + g) * S_ + s];
    const size_t off = (size_t)bs * C_;
    float4 r = make_float4(0.f, 0.f, 0.f, 0.f);
    if (m) r = reinterpret_cast<const float4*>(x + off)[t];
    reinterpret_cast<float4*>(out + off)[t] = r;
}

extern "C" void kernel_launch(void* const* d_in, const int* in_sizes, int n_in,
                              void* d_out, int out_size) {
    const float* x = (const float*)d_in[0];
    float* out = (float*)d_out;
    k_norms <<<B_ * S_, 256>>>(x);
    k_select<<<B_ * G_, 1024>>>();
    k_apply <<<B_ * S_, 256>>>(x, out);
}

// round 2
// speedup vs baseline: 1.6209x; 1.6209x over previous
#include <cuda_runtime.h>
#include <cstdint>

#define B_  32
#define S_  2048
#define C_  1024
#define G_  16
#define K_  256

__device__ float         g_norms[B_ * G_ * S_];   // (B*g, S) row-major
__device__ unsigned char g_mask [B_ * G_ * S_];

// ---------------------------------------------------------------------------
// K1: sum-of-squares per (b,s,group). 8 bs-rows per block, 256 threads.
// Front-batched loads -> MLP=8.
// ---------------------------------------------------------------------------
__global__ __launch_bounds__(256) void k_norms(const float* __restrict__ x) {
    const int base_bs = blockIdx.x << 3;    // 8 rows per block
    const int t = threadIdx.x;
    float4 v[8];
    #pragma unroll
    for (int r = 0; r < 8; r++)
        v[r] = reinterpret_cast<const float4*>(x + (size_t)(base_bs + r) * C_)[t];
    #pragma unroll
    for (int r = 0; r < 8; r++) {
        float ss = v[r].x * v[r].x + v[r].y * v[r].y
                 + v[r].z * v[r].z + v[r].w * v[r].w;
        #pragma unroll
        for (int off = 8; off > 0; off >>= 1)
            ss += __shfl_down_sync(0xffffffffu, ss, off, 16);
        if ((t & 15) == 0) {
            const int bs = base_bs + r;
            const int b  = bs >> 11;        // /S_
            const int s  = bs & (S_ - 1);
            g_norms[((b << 4) + (t >> 4)) * S_ + s] = ss;
        }
    }
}

// ---------------------------------------------------------------------------
// K2: exact Kth-largest per row via 4-pass radix select (values >= 0, so the
// raw uint bit pattern is order-preserving). Then exact-K mask with tie fill.
// 512 blocks x 256 threads.
// ---------------------------------------------------------------------------
__global__ __launch_bounds__(256) void k_select() {
    __shared__ unsigned int vals[S_];
    __shared__ int hist[256];
    __shared__ int sh_k;
    __shared__ unsigned int sh_prefix;
    __shared__ int n_gt, eq_cnt;

    const int row = blockIdx.x;
    const int tid = threadIdx.x;
    const float* nr = g_norms + (size_t)row * S_;

    #pragma unroll
    for (int i = tid; i < S_; i += 256)
        vals[i] = __float_as_uint(nr[i]);   // ss >= 0 -> monotone uint
    if (tid == 0) { sh_k = K_; sh_prefix = 0u; n_gt = 0; eq_cnt = 0; }
    __syncthreads();

    int k = K_;
    unsigned int prefix = 0u;
    #pragma unroll
    for (int shift = 24; shift >= 0; shift -= 8) {
        hist[tid] = 0;
        __syncthreads();
        const unsigned int pmask =
            (shift == 24) ? 0u : (0xFFFFFFFFu << (shift + 8));
        #pragma unroll
        for (int i = tid; i < S_; i += 256) {
            unsigned int u = vals[i];
            if ((u & pmask) == prefix)
                atomicAdd(&hist[(u >> shift) & 255], 1);
        }
        __syncthreads();

        if (tid < 32) {
            const int binbase = 255 - tid * 8;   // lane 0 owns the top bins
            int c = 0;
            #pragma unroll
            for (int j = 0; j < 8; j++) c += hist[binbase - j];
            // inclusive scan across lanes (descending bin order)
            int inc = c;
            #pragma unroll
            for (int off = 1; off < 32; off <<= 1) {
                int nth = __shfl_up_sync(0xffffffffu, inc, off);
                if (tid >= off) inc += nth;
            }
            const int pre = inc - c;
            const bool hit = (pre < k) && (pre + c >= k);
            const unsigned int bal = __ballot_sync(0xffffffffu, hit);
            if (tid == (__ffs(bal) - 1)) {
                int cum = pre;
                #pragma unroll
                for (int j = 0; j < 8; j++) {
                    const int h = hist[binbase - j];
                    if (cum + h >= k) {
                        sh_k = k - cum;
                        sh_prefix = prefix |
                            ((unsigned int)(binbase - j) << shift);
                        break;
                    }
                    cum += h;
                }
            }
        }
        __syncthreads();
        k = sh_k;
        prefix = sh_prefix;
        __syncthreads();
    }

    const float thr = __uint_as_float(prefix);   // exact Kth largest value

    // exact-K mask: all strictly greater, then fill among equals
    int loc = 0;
    #pragma unroll
    for (int i = tid; i < S_; i += 256)
        loc += (__uint_as_float(vals[i]) > thr) ? 1 : 0;
    #pragma unroll
    for (int off = 16; off > 0; off >>= 1)
        loc += __shfl_down_sync(0xffffffffu, loc, off);
    if ((tid & 31) == 0) atomicAdd(&n_gt, loc);
    __syncthreads();

    const int ngt = n_gt;
    unsigned char* mrow = g_mask + (size_t)row * S_;
    #pragma unroll
    for (int i = tid; i < S_; i += 256) {
        const float v = __uint_as_float(vals[i]);
        unsigned char m = 0;
        if (v > thr) m = 1;
        else if (v == thr) {
            const int p = atomicAdd(&eq_cnt, 1);
            m = (ngt + p < K_) ? 1 : 0;
        }
        mrow[i] = m;
    }
}

// ---------------------------------------------------------------------------
// K3: apply mask. 4 bs-rows per block, 256 threads; batched mask loads and
// predicated float4 loads (MLP=4), unconditional float4 stores.
// ---------------------------------------------------------------------------
__global__ __launch_bounds__(256) void k_apply(const float* __restrict__ x,
                                               float* __restrict__ out) {
    const int base_bs = blockIdx.x << 2;
    const int t = threadIdx.x;
    const int g = t >> 4;

    unsigned char m[4];
    #pragma unroll
    for (int r = 0; r < 4; r++) {
        const int bs = base_bs + r;
        const int b  = bs >> 11;
        const int s  = bs & (S_ - 1);
        m[r] = __ldg(&g_mask[((b << 4) + g) * S_ + s]);
    }

    float4 v[4];
    #pragma unroll
    for (int r = 0; r < 4; r++) {
        v[r] = make_float4(0.f, 0.f, 0.f, 0.f);
        if (m[r])
            v[r] = reinterpret_cast<const float4*>(
                       x + (size_t)(base_bs + r) * C_)[t];
    }
    #pragma unroll
    for (int r = 0; r < 4; r++)
        reinterpret_cast<float4*>(out + (size_t)(base_bs + r) * C_)[t] = v[r];
}

extern "C" void kernel_launch(void* const* d_in, const int* in_sizes, int n_in,
                              void* d_out, int out_size) {
    const float* x = (const float*)d_in[0];
    float* out = (float*)d_out;
    k_norms <<<(B_ * S_) / 8, 256>>>(x);
    k_select<<<B_ * G_, 256>>>();
    k_apply <<<(B_ * S_) / 4, 256>>>(x, out);
}

// round 3
// speedup vs baseline: 1.6405x; 1.0121x over previous
#include <cuda_runtime.h>
#include <cstdint>

#define B_  32
#define S_  2048
#define C_  1024
#define G_  16
#define K_  256

__device__ float         g_norms[B_ * G_ * S_];   // (B*g, S) row-major
__device__ unsigned char g_mask [B_ * G_ * S_];

// ---------------------------------------------------------------------------
// K1: sum-of-squares per (b,s,group). 8 bs-rows per block, 256 threads,
// front-batched streaming loads (MLP=8).
// ---------------------------------------------------------------------------
__global__ __launch_bounds__(256) void k_norms(const float* __restrict__ x) {
    const int base_bs = blockIdx.x << 3;
    const int t = threadIdx.x;
    float4 v[8];
    #pragma unroll
    for (int r = 0; r < 8; r++)
        v[r] = __ldcs(reinterpret_cast<const float4*>(
                          x + (size_t)(base_bs + r) * C_) + t);
    #pragma unroll
    for (int r = 0; r < 8; r++) {
        float ss = v[r].x * v[r].x + v[r].y * v[r].y
                 + v[r].z * v[r].z + v[r].w * v[r].w;
        #pragma unroll
        for (int off = 8; off > 0; off >>= 1)
            ss += __shfl_down_sync(0xffffffffu, ss, off, 16);
        if ((t & 15) == 0) {
            const int bs = base_bs + r;
            const int b  = bs >> 11;
            const int s  = bs & (S_ - 1);
            g_norms[((b << 4) + (t >> 4)) * S_ + s] = ss;
        }
    }
}

// ---------------------------------------------------------------------------
// K2: exact Kth-largest per row via 4-pass radix select on the monotone uint
// encoding (values >= 0). Exact-K mask with tie fill. 512 blocks x 256 thr.
// ---------------------------------------------------------------------------
__global__ __launch_bounds__(256) void k_select() {
    __shared__ unsigned int vals[S_];
    __shared__ int hist[256];
    __shared__ int sh_k;
    __shared__ unsigned int sh_prefix;
    __shared__ int n_gt, eq_cnt;

    const int row = blockIdx.x;
    const int tid = threadIdx.x;
    const float* nr = g_norms + (size_t)row * S_;

    #pragma unroll
    for (int i = tid; i < S_; i += 256)
        vals[i] = __float_as_uint(nr[i]);
    if (tid == 0) { sh_k = K_; sh_prefix = 0u; n_gt = 0; eq_cnt = 0; }
    hist[tid] = 0;
    __syncthreads();

    int k = K_;
    unsigned int prefix = 0u;
    #pragma unroll
    for (int shift = 24; shift >= 0; shift -= 8) {
        // histogram of this byte among survivors of prefix
        if (shift == 24) {
            #pragma unroll
            for (int i = tid; i < S_; i += 256)
                atomicAdd(&hist[vals[i] >> 24], 1);
        } else {
            const unsigned int pmask = 0xFFFFFFFFu << (shift + 8);
            #pragma unroll
            for (int i = tid; i < S_; i += 256) {
                const unsigned int u = vals[i];
                if ((u & pmask) == prefix)
                    atomicAdd(&hist[(u >> shift) & 255], 1);
            }
        }
        __syncthreads();

        if (tid < 32) {
            const int binbase = 255 - tid * 8;  // lane 0 owns top bins
            int c = 0;
            #pragma unroll
            for (int j = 0; j < 8; j++) c += hist[binbase - j];
            int inc = c;
            #pragma unroll
            for (int off = 1; off < 32; off <<= 1) {
                const int nth = __shfl_up_sync(0xffffffffu, inc, off);
                if (tid >= off) inc += nth;
            }
            const int pre = inc - c;
            const bool hit = (pre < k) && (pre + c >= k);
            const unsigned int bal = __ballot_sync(0xffffffffu, hit);
            if (tid == (__ffs(bal) - 1)) {
                int cum = pre;
                #pragma unroll
                for (int j = 0; j < 8; j++) {
                    const int h = hist[binbase - j];
                    if (cum + h >= k) {
                        sh_k = k - cum;
                        sh_prefix = prefix |
                            ((unsigned int)(binbase - j) << shift);
                        break;
                    }
                    cum += h;
                }
            }
        }
        __syncthreads();
        k = sh_k;
        prefix = sh_prefix;
        hist[tid] = 0;          // safe: scan already consumed hist
        __syncthreads();
    }

    const float thr = __uint_as_float(prefix);  // exact Kth largest

    int loc = 0;
    #pragma unroll
    for (int i = tid; i < S_; i += 256)
        loc += (__uint_as_float(vals[i]) > thr) ? 1 : 0;
    #pragma unroll
    for (int off = 16; off > 0; off >>= 1)
        loc += __shfl_down_sync(0xffffffffu, loc, off);
    if ((tid & 31) == 0) atomicAdd(&n_gt, loc);
    __syncthreads();

    const int ngt = n_gt;
    unsigned char* mrow = g_mask + (size_t)row * S_;
    #pragma unroll
    for (int i = tid; i < S_; i += 256) {
        const float v = __uint_as_float(vals[i]);
        unsigned char m = 0;
        if (v > thr) m = 1;
        else if (v == thr) {
            const int p = atomicAdd(&eq_cnt, 1);
            m = (ngt + p < K_) ? 1 : 0;
        }
        mrow[i] = m;
    }
}

// ---------------------------------------------------------------------------
// K3: apply mask. 8 bs-rows per block; one uint64 load fetches all 8 mask
// bytes per thread (same (b,g) row, consecutive s). Front-batched predicated
// float4 streaming loads, streaming stores. MLP=8.
// ---------------------------------------------------------------------------
__global__ __launch_bounds__(256) void k_apply(const float* __restrict__ x,
                                               float* __restrict__ out) {
    const int base_bs = blockIdx.x << 3;   // aligned to 8; same b for all 8
    const int t  = threadIdx.x;
    const int g  = t >> 4;
    const int b  = base_bs >> 11;
    const int s0 = base_bs & (S_ - 1);

    const unsigned long long mbits =
        *reinterpret_cast<const unsigned long long*>(
            &g_mask[(size_t)((b << 4) + g) * S_ + s0]);

    float4 v[8];
    #pragma unroll
    for (int r = 0; r < 8; r++) {
        v[r] = make_float4(0.f, 0.f, 0.f, 0.f);
        if ((mbits >> (r << 3)) & 0xFFull)
            v[r] = __ldcs(reinterpret_cast<const float4*>(
                              x + (size_t)(base_bs + r) * C_) + t);
    }
    #pragma unroll
    for (int r = 0; r < 8; r++)
        __stcs(reinterpret_cast<float4*>(
                   out + (size_t)(base_bs + r) * C_) + t, v[r]);
}

extern "C" void kernel_launch(void* const* d_in, const int* in_sizes, int n_in,
                              void* d_out, int out_size) {
    const float* x = (const float*)d_in[0];
    float* out = (float*)d_out;
    k_norms <<<(B_ * S_) / 8, 256>>>(x);
    k_select<<<B_ * G_, 256>>>();
    k_apply <<<(B_ * S_) / 8, 256>>>(x, out);
}